// round 1
// baseline (speedup 1.0000x reference)
#include <cuda_runtime.h>
#include <cuda_bf16.h>

// LengthRegulator: out[b,t,:] = x[b, searchsorted(cumsum(dur[b]), t, 'right'), :]
// masked to zero where t >= total[b]. mel_mask appended to d_out as float 0/1.

#define BB 32
#define NN 1024
#define DD 384
#define ML 4096
#define D4 (DD / 4)   // 96 float4 per row

__device__ int g_cum[BB][NN];
__device__ int g_total[BB];

// ---------------- K1: per-batch inclusive scan of durations ----------------
__global__ void __launch_bounds__(NN) scan_kernel(const int* __restrict__ dur) {
    const int b = blockIdx.x;
    const int t = threadIdx.x;
    const int lane = t & 31;
    const int w    = t >> 5;

    int val = dur[b * NN + t];

    // warp inclusive scan
    #pragma unroll
    for (int o = 1; o < 32; o <<= 1) {
        int n = __shfl_up_sync(0xFFFFFFFFu, val, o);
        if (lane >= o) val += n;
    }

    __shared__ int wsum[32];
    if (lane == 31) wsum[w] = val;
    __syncthreads();

    if (w == 0) {
        int s = wsum[lane];
        #pragma unroll
        for (int o = 1; o < 32; o <<= 1) {
            int n = __shfl_up_sync(0xFFFFFFFFu, s, o);
            if (lane >= o) s += n;
        }
        wsum[lane] = s;
    }
    __syncthreads();

    int excl = (w > 0) ? wsum[w - 1] : 0;
    int cum  = val + excl;

    g_cum[b][t] = cum;
    if (t == NN - 1) g_total[b] = cum;
}

// ---------------- K2: searchsorted + gather + mask, fused ----------------
// blockDim = (96, 4): threadIdx.y = row within block, threadIdx.x = float4 lane.
// grid = (ML/4, BB)
__global__ void __launch_bounds__(D4 * 4) expand_kernel(
    const float* __restrict__ x,
    float* __restrict__ out,
    float* __restrict__ mask_out,   // may be null
    int write_mask
) {
    const int b = blockIdx.y;
    const int t = blockIdx.x * 4 + threadIdx.y;

    __shared__ int s_idx[4];
    __shared__ int s_msk[4];

    if (threadIdx.x == 0) {
        const int total = g_total[b];
        const int m = (t >= total) ? 1 : 0;

        // searchsorted(cum, t, side='right') == first i with cum[i] > t
        const int* __restrict__ cum = g_cum[b];
        int lo = 0, hi = NN;
        while (lo < hi) {
            int mid = (lo + hi) >> 1;
            if (cum[mid] <= t) lo = mid + 1; else hi = mid;
        }
        int idx = lo < (NN - 1) ? lo : (NN - 1);

        s_idx[threadIdx.y] = idx;
        s_msk[threadIdx.y] = m;
        if (write_mask) mask_out[(size_t)b * ML + t] = (float)m;
    }
    __syncthreads();

    const int idx = s_idx[threadIdx.y];
    const int m   = s_msk[threadIdx.y];

    float4* __restrict__ dst =
        (float4*)(out + ((size_t)b * ML + t) * DD);

    float4 v;
    if (m) {
        v = make_float4(0.f, 0.f, 0.f, 0.f);
    } else {
        const float4* __restrict__ src =
            (const float4*)(x + ((size_t)b * NN + idx) * DD);
        v = src[threadIdx.x];
    }
    dst[threadIdx.x] = v;
}

extern "C" void kernel_launch(void* const* d_in, const int* in_sizes, int n_in,
                              void* d_out, int out_size) {
    const float* x   = (const float*)d_in[0];
    const int*   dur = (const int*)d_in[1];
    float*       out = (float*)d_out;

    // mask appended after the main output if the buffer is big enough
    const long long out_elems  = (long long)BB * ML * DD;
    const long long mask_elems = (long long)BB * ML;
    int write_mask = ((long long)out_size >= out_elems + mask_elems) ? 1 : 0;
    float* mask_out = write_mask ? (out + out_elems) : nullptr;

    scan_kernel<<<BB, NN>>>(dur);

    dim3 block(D4, 4);
    dim3 grid(ML / 4, BB);
    expand_kernel<<<grid, block>>>(x, out, mask_out, write_mask);
}

// round 3
// speedup vs baseline: 3.4011x; 3.4011x over previous
#include <cuda_runtime.h>
#include <cuda_bf16.h>

// LengthRegulator: out[b,t,:] = x[b, searchsorted(cumsum(dur[b]), t, 'right'), :]
// zeroed where t >= total[b]. mel_mask appended to d_out as float 0/1.

#define BB 32
#define NN 1024
#define DD 384
#define ML 4096
#define D4 (DD / 4)           // 96 float4 per row
#define NROWS (BB * ML)       // 131072 output rows
#define ROWS_PER_WARP 2
#define K2_BLOCK 256

// per output row: source offset in float4 units, or -1 if masked
__device__ int g_meta[NROWS];

// ---- K1: scan durations + all binary searches + mask, one block per batch ----
__global__ void __launch_bounds__(NN) prep_kernel(
    const int* __restrict__ dur,
    float* __restrict__ mask_out,
    int write_mask
) {
    const int b = blockIdx.x;
    const int t = threadIdx.x;
    const int lane = t & 31;
    const int w    = t >> 5;

    __shared__ int s_cum[NN];
    __shared__ int wsum[32];

    int val = dur[b * NN + t];

    #pragma unroll
    for (int o = 1; o < 32; o <<= 1) {
        int n = __shfl_up_sync(0xFFFFFFFFu, val, o);
        if (lane >= o) val += n;
    }
    if (lane == 31) wsum[w] = val;
    __syncthreads();
    if (w == 0) {
        int s = wsum[lane];
        #pragma unroll
        for (int o = 1; o < 32; o <<= 1) {
            int n = __shfl_up_sync(0xFFFFFFFFu, s, o);
            if (lane >= o) s += n;
        }
        wsum[lane] = s;
    }
    __syncthreads();
    int cum = val + ((w > 0) ? wsum[w - 1] : 0);
    s_cum[t] = cum;
    __syncthreads();

    const int total = s_cum[NN - 1];

    // each thread does ML/NN = 4 searches against shared cum.
    // branch-free lower-bound by power-of-two steps: pos = #elements <= tt
    #pragma unroll
    for (int k = 0; k < ML / NN; k++) {
        const int tt = t + k * NN;
        int pos = 0;
        #pragma unroll
        for (int step = NN >> 1; step >= 1; step >>= 1) {
            int np = pos + step;                 // np <= NN always
            if (s_cum[np - 1] <= tt) pos = np;
        }
        const int masked = (tt >= total);
        const int idx = pos < (NN - 1) ? pos : (NN - 1);
        g_meta[b * ML + tt] = masked ? -1 : (b * NN + idx) * D4;
        if (write_mask) mask_out[b * ML + tt] = (float)masked;
    }
}

// ---- K2: pure copy, warp handles ROWS_PER_WARP rows, 3 float4 per lane/row ----
__global__ void __launch_bounds__(K2_BLOCK) copy_kernel(
    const float4* __restrict__ x4,
    float4* __restrict__ out4
) {
    const int gw   = (blockIdx.x * K2_BLOCK + threadIdx.x) >> 5;
    const int lane = threadIdx.x & 31;
    const int row0 = gw * ROWS_PER_WARP;

    const int m0 = g_meta[row0];
    const int m1 = g_meta[row0 + 1];

    float4 v[6];
    const float4 z = make_float4(0.f, 0.f, 0.f, 0.f);

    if (m0 >= 0) {
        v[0] = x4[m0 + lane];
        v[1] = x4[m0 + lane + 32];
        v[2] = x4[m0 + lane + 64];
    } else { v[0] = z; v[1] = z; v[2] = z; }

    if (m1 >= 0) {
        v[3] = x4[m1 + lane];
        v[4] = x4[m1 + lane + 32];
        v[5] = x4[m1 + lane + 64];
    } else { v[3] = z; v[4] = z; v[5] = z; }

    float4* d0 = out4 + (size_t)row0 * D4;
    d0[lane]          = v[0];
    d0[lane + 32]     = v[1];
    d0[lane + 64]     = v[2];
    float4* d1 = d0 + D4;
    d1[lane]          = v[3];
    d1[lane + 32]     = v[4];
    d1[lane + 64]     = v[5];
}

extern "C" void kernel_launch(void* const* d_in, const int* in_sizes, int n_in,
                              void* d_out, int out_size) {
    const float* x   = (const float*)d_in[0];
    const int*   dur = (const int*)d_in[1];
    float*       out = (float*)d_out;

    const long long out_elems  = (long long)NROWS * DD;
    const long long mask_elems = (long long)NROWS;
    int write_mask = ((long long)out_size >= out_elems + mask_elems) ? 1 : 0;
    float* mask_out = write_mask ? (out + out_elems) : nullptr;

    prep_kernel<<<BB, NN>>>(dur, mask_out, write_mask);

    const int warps  = NROWS / ROWS_PER_WARP;            // 65536
    const int blocks = warps * 32 / K2_BLOCK;            // 8192
    copy_kernel<<<blocks, K2_BLOCK>>>((const float4*)x, (float4*)out);
}